// round 8
// baseline (speedup 1.0000x reference)
#include <cuda_runtime.h>
#include <cstdint>

#define BSZ  8
#define CDIM 64
#define NPTS 4096
#define KNN  20
#define OC   64
#define QT   64          // queries per block in k_knn

// ---------------- scratch (device globals; no allocation) ----------------
__device__ float g_sq [BSZ*NPTS];
__device__ float g_u  [BSZ*NPTS*OC];
__device__ float g_v  [BSZ*NPTS*OC];
__device__ int   g_idx[BSZ*NPTS*KNN];
__device__ float g_mxv[BSZ*NPTS*OC];
__device__ float g_mnv[BSZ*NPTS*OC];
__device__ float g_S1[OC];
__device__ float g_S2[OC];
__device__ float g_ga[OC];
__device__ float g_gb[OC];

// ---------------- kernel 0: squared norms + zero stats ----------------
__global__ __launch_bounds__(256) void k_sq(const float* __restrict__ x) {
    const int b = blockIdx.y;
    const int n = blockIdx.x * 256 + threadIdx.x;
    const float* xb = x + (size_t)b * CDIM * NPTS;
    float s = 0.f;
#pragma unroll 8
    for (int c = 0; c < CDIM; ++c) {
        float t = xb[c * NPTS + n];
        s += t * t;
    }
    g_sq[b * NPTS + n] = s;
    if (blockIdx.x == 0 && blockIdx.y == 0 && threadIdx.x < OC) {
        g_S1[threadIdx.x] = 0.f;
        g_S2[threadIdx.x] = 0.f;
    }
}

// ---------------- kernel A: u = W1*x, v = (W2-W1)*x, layout [b][n][o] ---
__global__ __launch_bounds__(256) void k_uv(const float* __restrict__ x,
                                            const float* __restrict__ W) {
    __shared__ float Wc[128 * 64];
    __shared__ float xt[64 * 32];
    const int b = blockIdx.y, n0 = blockIdx.x * 32;
    const int tx = threadIdx.x, ty = threadIdx.y, tid = ty * 16 + tx;

    for (int i = tid; i < 128 * 64; i += 256) {
        int r = i >> 6, c = i & 63;
        float wv;
        if (r < 64) wv = W[r * 128 + c];
        else        wv = W[(r - 64) * 128 + 64 + c] - W[(r - 64) * 128 + c];
        Wc[i] = wv;
    }
    const float* xb = x + (size_t)b * CDIM * NPTS;
    for (int i = tid; i < 64 * 32; i += 256) {
        int c = i >> 5, nn = i & 31;
        xt[i] = xb[c * NPTS + n0 + nn];
    }
    __syncthreads();

    float acc[8][2] = {};
#pragma unroll 8
    for (int c = 0; c < 64; ++c) {
        float2 bv = *(const float2*)&xt[c * 32 + tx * 2];
#pragma unroll
        for (int i = 0; i < 8; ++i) {
            float a = Wc[(ty * 8 + i) * 64 + c];
            acc[i][0] += a * bv.x;
            acc[i][1] += a * bv.y;
        }
    }
    __syncthreads();

    if (ty < 8) {
#pragma unroll
        for (int i = 0; i < 8; ++i) {
            Wc[(tx * 2 + 0) * 65 + ty * 8 + i] = acc[i][0];
            Wc[(tx * 2 + 1) * 65 + ty * 8 + i] = acc[i][1];
        }
    }
    __syncthreads();
    {
        float* dst = g_u + ((size_t)b * NPTS + n0) * OC;
        for (int i = tid; i < 32 * 64; i += 256) {
            int nn = i >> 6, oo = i & 63;
            dst[i] = Wc[nn * 65 + oo];
        }
    }
    __syncthreads();
    if (ty >= 8) {
#pragma unroll
        for (int i = 0; i < 8; ++i) {
            Wc[(tx * 2 + 0) * 65 + (ty - 8) * 8 + i] = acc[i][0];
            Wc[(tx * 2 + 1) * 65 + (ty - 8) * 8 + i] = acc[i][1];
        }
    }
    __syncthreads();
    {
        float* dst = g_v + ((size_t)b * NPTS + n0) * OC;
        for (int i = tid; i < 32 * 64; i += 256) {
            int nn = i >> 6, oo = i & 63;
            dst[i] = Wc[nn * 65 + oo];
        }
    }
}

// ---------------- kernel B: mma.sync tf32 (3x split) Gram + top-K -------
// smem layout (bytes). Operand layout per split: [kg:8][point:64][k&3:4][{k,k+4}:2]
// row stride = 10 words (8 payload + 2 pad) to spread banks; v2-aligned.
#define RSW     10
#define KGW     (64 * RSW)          // 640 words per k-group
#define SPLIT_B 20480               // bytes per split region (8*640*4)
#define SM_AHI  0
#define SM_ALO  (SM_AHI + SPLIT_B)
#define SM_BHI  (SM_ALO + SPLIT_B)
#define SM_BLO  (SM_BHI + SPLIT_B)
#define SM_KEYS (SM_BLO + SPLIT_B)  // float[64][68]
#define SM_SQS  (SM_KEYS + 64 * 68 * 4)
#define SM_BYTES (SM_SQS + 2 * 64 * 4)   // 99840 bytes

__device__ __forceinline__ uint32_t smem_u32(const void* p) {
    uint32_t a;
    asm("{ .reg .u64 t; cvta.to.shared.u64 t, %1; cvt.u32.u64 %0, t; }"
        : "=r"(a) : "l"(p));
    return a;
}

__device__ __forceinline__ void sts_split(char* smc, int region_hi, int c,
                                          int pt, float v) {
    uint32_t h;
    asm("cvt.rna.tf32.f32 %0, %1;" : "=r"(h) : "f"(v));
    float lof = v - __uint_as_float(h);
    uint32_t l;
    asm("cvt.rna.tf32.f32 %0, %1;" : "=r"(l) : "f"(lof));
    int woff = (c >> 3) * KGW + pt * RSW + (c & 3) * 2 + ((c >> 2) & 1);
    *(uint32_t*)(smc + region_hi + woff * 4) = h;
    *(uint32_t*)(smc + region_hi + SPLIT_B + woff * 4) = l;
}

#define LDSV2(r0_, r1_, addr_) \
    asm volatile("ld.shared.v2.b32 {%0,%1}, [%2];" \
                 : "=r"(r0_), "=r"(r1_) : "r"(addr_))

#define MMA_TF32(c_, a0_, a1_, a2_, a3_, b0_, b1_) \
    asm volatile("mma.sync.aligned.m16n8k8.row.col.f32.tf32.tf32.f32 " \
                 "{%0,%1,%2,%3}, {%4,%5,%6,%7}, {%8,%9}, {%0,%1,%2,%3};" \
                 : "+f"((c_)[0]), "+f"((c_)[1]), "+f"((c_)[2]), "+f"((c_)[3]) \
                 : "r"(a0_), "r"(a1_), "r"(a2_), "r"(a3_), "r"(b0_), "r"(b1_))

__device__ __forceinline__ void insert_cand(float k, int m, float& tk, int& ti,
                                            float& thr, int& minl, int lane) {
    unsigned bal = __ballot_sync(0xffffffffu, k > thr);
    while (bal) {
        int src = __ffs(bal) - 1;
        bal &= bal - 1;
        float ck = __shfl_sync(0xffffffffu, k, src);
        int   cm = __shfl_sync(0xffffffffu, m, src);
        if (ck > thr) {                  // re-check: thr may have risen
            if (lane == minl) { tk = ck; ti = cm; }
            float mv = (lane < KNN) ? tk : 3.4e38f;
            int   ml = lane;
#pragma unroll
            for (int off = 16; off; off >>= 1) {
                float ov = __shfl_xor_sync(0xffffffffu, mv, off);
                int   ol = __shfl_xor_sync(0xffffffffu, ml, off);
                if (ov < mv || (ov == mv && ol < ml)) { mv = ov; ml = ol; }
            }
            thr = mv; minl = ml;         // uniform across warp
        }
    }
}

__global__ __launch_bounds__(256, 2) void k_knn(const float* __restrict__ x) {
    extern __shared__ char smc[];
    const uint32_t smb = smem_u32(smc);
    float* keysf = (float*)(smc + SM_KEYS);
    float* sqf   = (float*)(smc + SM_SQS);

    const int tid = threadIdx.x;
    const int warp = tid >> 5, lane = tid & 31;
    const int b  = blockIdx.y;
    const int q0 = blockIdx.x * QT;
    const float* xb = x + (size_t)b * CDIM * NPTS;

    // warp microtile: rows r0..r0+15, cols c0..c0+31 of the 64x64 key tile
    const int r0 = (warp >> 1) * 16;
    const int c0 = (warp & 1) * 32;
    const int rowA = r0 + (lane >> 2);
    const int nB   = c0 + (lane >> 2);

    // fragment smem addresses (byte)
    const uint32_t aHi = smb + SM_AHI + (uint32_t)(rowA * RSW + (lane & 3) * 2) * 4;
    const uint32_t aLo = aHi + SPLIT_B;
    const uint32_t bHi = smb + SM_BHI + (uint32_t)(nB * RSW + (lane & 3) * 2) * 4;
    const uint32_t bLo = bHi + SPLIT_B;

    // ---- prologue: build A (tf32 split) + B tile 0 + sqs[0] ----
    {
        const int c = tid >> 2, mg = tid & 3;
#pragma unroll
        for (int q = 0; q < 4; ++q) {
            float4 v = *(const float4*)&xb[c * NPTS + q0 + mg * 16 + q * 4];
            int pt = mg * 16 + q * 4;
            sts_split(smc, SM_AHI, c, pt + 0, v.x);
            sts_split(smc, SM_AHI, c, pt + 1, v.y);
            sts_split(smc, SM_AHI, c, pt + 2, v.z);
            sts_split(smc, SM_AHI, c, pt + 3, v.w);
        }
#pragma unroll
        for (int q = 0; q < 4; ++q) {
            float4 v = *(const float4*)&xb[c * NPTS + 0 + mg * 16 + q * 4];
            int pt = mg * 16 + q * 4;
            sts_split(smc, SM_BHI, c, pt + 0, v.x);
            sts_split(smc, SM_BHI, c, pt + 1, v.y);
            sts_split(smc, SM_BHI, c, pt + 2, v.z);
            sts_split(smc, SM_BHI, c, pt + 3, v.w);
        }
        if (tid < 64) sqf[tid] = g_sq[b * NPTS + tid];
    }
    __syncthreads();

    float tk[8], thr[8];
    int   ti[8], minl[8];
#pragma unroll
    for (int r = 0; r < 8; ++r) {
        tk[r] = -3.4e38f; ti[r] = 0; thr[r] = -3.4e38f; minl[r] = 0;
    }

    for (int t = 0; t < NPTS / 64; ++t) {
        const int m0 = t * 64;

        // stage next B tile into registers (LDG latency hidden under MMA)
        float4 st[4];
        float sqst = 0.f;
        if (t + 1 < NPTS / 64) {
            const int c = tid >> 2, mg = tid & 3;
            const int m0n = m0 + 64;
#pragma unroll
            for (int q = 0; q < 4; ++q)
                st[q] = *(const float4*)&xb[c * NPTS + m0n + mg * 16 + q * 4];
            if (tid < 64) sqst = g_sq[b * NPTS + m0n + tid];
        }

        // ---- 3x-split tf32 MMA over K=64 ----
        float acc[4][4];
#pragma unroll
        for (int j = 0; j < 4; ++j)
#pragma unroll
            for (int q = 0; q < 4; ++q) acc[j][q] = 0.f;

#pragma unroll
        for (int kg = 0; kg < 8; ++kg) {
            const uint32_t kgo = kg * (KGW * 4);
            uint32_t ah0, ah1, ah2, ah3;
            LDSV2(ah0, ah2, aHi + kgo);
            LDSV2(ah1, ah3, aHi + kgo + 8 * RSW * 4);
            uint32_t bh[8];
#pragma unroll
            for (int j = 0; j < 4; ++j)
                LDSV2(bh[2 * j], bh[2 * j + 1], bHi + kgo + j * 8 * RSW * 4);
#pragma unroll
            for (int j = 0; j < 4; ++j)
                MMA_TF32(acc[j], ah0, ah1, ah2, ah3, bh[2 * j], bh[2 * j + 1]);
            uint32_t bl0, bl1;
#pragma unroll
            for (int j = 0; j < 4; ++j) {
                LDSV2(bl0, bl1, bLo + kgo + j * 8 * RSW * 4);
                MMA_TF32(acc[j], ah0, ah1, ah2, ah3, bl0, bl1);
            }
            uint32_t al0, al1, al2, al3;
            LDSV2(al0, al2, aLo + kgo);
            LDSV2(al1, al3, aLo + kgo + 8 * RSW * 4);
#pragma unroll
            for (int j = 0; j < 4; ++j)
                MMA_TF32(acc[j], al0, al1, al2, al3, bh[2 * j], bh[2 * j + 1]);
        }

        // epilogue: raw dot products -> block keys tile
        {
            const int rlo = r0 + (lane >> 2);
#pragma unroll
            for (int j = 0; j < 4; ++j) {
                const int cb = c0 + j * 8 + (lane & 3) * 2;
                keysf[rlo * 68 + cb]           = acc[j][0];
                keysf[rlo * 68 + cb + 1]       = acc[j][1];
                keysf[(rlo + 8) * 68 + cb]     = acc[j][2];
                keysf[(rlo + 8) * 68 + cb + 1] = acc[j][3];
            }
        }
        __syncthreads();   // keys complete; all MMA reads of Bp done

        // ---- selection: warp w owns rows 8w..8w+7 ----
        {
            const float* sqcur = sqf + (t & 1) * 64;
            const float sql = sqcur[lane];
            const float sqh = sqcur[32 + lane];
#pragma unroll
            for (int r = 0; r < 8; ++r) {
                const float* krow = keysf + (warp * 8 + r) * 68;
                float k0 = fmaf(2.f, krow[lane], -sql);
                float k1 = fmaf(2.f, krow[32 + lane], -sqh);
                insert_cand(k0, m0 + lane,      tk[r], ti[r], thr[r], minl[r], lane);
                insert_cand(k1, m0 + 32 + lane, tk[r], ti[r], thr[r], minl[r], lane);
            }
        }

        // ---- producer: split staged regs -> Bp, sqs for next tile ----
        if (t + 1 < NPTS / 64) {
            const int c = tid >> 2, mg = tid & 3;
#pragma unroll
            for (int q = 0; q < 4; ++q) {
                int pt = mg * 16 + q * 4;
                sts_split(smc, SM_BHI, c, pt + 0, st[q].x);
                sts_split(smc, SM_BHI, c, pt + 1, st[q].y);
                sts_split(smc, SM_BHI, c, pt + 2, st[q].z);
                sts_split(smc, SM_BHI, c, pt + 3, st[q].w);
            }
            if (tid < 64) sqf[((t + 1) & 1) * 64 + tid] = sqst;
        }
        __syncthreads();   // Bp/sqs ready; keys fully consumed
    }

    if (lane < KNN) {
#pragma unroll
        for (int r = 0; r < 8; ++r)
            g_idx[((size_t)b * NPTS + q0 + warp * 8 + r) * KNN + lane] = ti[r];
    }
}

// ---------------- kernel C: one gather pass: max/min + BN stats ----------
__global__ __launch_bounds__(256) void k_gather() {
    __shared__ int   sidx[4][KNN];
    __shared__ float red[2][4][64];
    const int o = threadIdx.x;
    const int py = threadIdx.y;
    const int tid = py * 64 + o;
    const int b = blockIdx.y;
    const int n0 = blockIdx.x * 64;
    const float* ub = g_u + (size_t)b * NPTS * OC;
    float s1 = 0.f, s2 = 0.f;

    for (int it = 0; it < 16; ++it) {
        __syncthreads();
        if (tid < 4 * KNN) {
            int g = tid / KNN, j = tid % KNN;
            sidx[g][j] = g_idx[((size_t)b * NPTS + n0 + it * 4 + g) * KNN + j];
        }
        __syncthreads();
        const int n = n0 + it * 4 + py;
        float s = 0.f, q = 0.f, mx = -3.4e38f, mn = 3.4e38f;
#pragma unroll
        for (int j = 0; j < KNN; ++j) {
            float val = ub[(size_t)sidx[py][j] * OC + o];
            s += val; q += val * val;
            mx = fmaxf(mx, val); mn = fminf(mn, val);
        }
        const size_t off = ((size_t)b * NPTS + n) * OC + o;
        float vv = g_v[off];
        g_mxv[off] = mx + vv;
        g_mnv[off] = mn + vv;
        s1 += (float)KNN * vv + s;
        s2 += (float)KNN * vv * vv + 2.f * vv * s + q;
    }
    red[0][py][o] = s1;
    red[1][py][o] = s2;
    __syncthreads();
    if (py == 0) {
        float a = red[0][0][o] + red[0][1][o] + red[0][2][o] + red[0][3][o];
        float c = red[1][0][o] + red[1][1][o] + red[1][2][o] + red[1][3][o];
        atomicAdd(&g_S1[o], a);
        atomicAdd(&g_S2[o], c);
    }
}

// ---------------- kernel D: finalize BN affine coefficients --------------
__global__ void k_finalize(const float* __restrict__ gamma,
                           const float* __restrict__ beta) {
    int o = threadIdx.x;
    const float M = (float)BSZ * (float)NPTS * (float)KNN;
    float mean = g_S1[o] / M;
    float var  = g_S2[o] / M - mean * mean;
    float a = gamma[o] * rsqrtf(var + 1e-5f);
    g_ga[o] = a;
    g_gb[o] = beta[o] - mean * a;
}

// ---------------- kernel E: affine + LeakyReLU + transpose to [b][o][n] --
__global__ __launch_bounds__(256) void k_out(float* __restrict__ out) {
    __shared__ float tile[64][65];
    const int o = threadIdx.x, ty = threadIdx.y;
    const int b = blockIdx.y, n0 = blockIdx.x * 64;
    const float a = g_ga[o], bc = g_gb[o];
#pragma unroll
    for (int it = 0; it < 16; ++it) {
        int nl = it * 4 + ty;
        size_t off = ((size_t)b * NPTS + n0 + nl) * OC + o;
        float raw = (a >= 0.f) ? g_mxv[off] : g_mnv[off];
        float val = fmaf(a, raw, bc);
        tile[nl][o] = (val >= 0.f) ? val : 0.2f * val;
    }
    __syncthreads();
#pragma unroll
    for (int it = 0; it < 16; ++it) {
        int oo = it * 4 + ty;
        out[((size_t)b * OC + oo) * NPTS + n0 + o] = tile[o][oo];
    }
}

// ---------------- launch ----------------
extern "C" void kernel_launch(void* const* d_in, const int* in_sizes, int n_in,
                              void* d_out, int out_size) {
    const float* x     = (const float*)d_in[0];
    const float* W     = (const float*)d_in[1];
    const float* gamma = (const float*)d_in[2];
    const float* beta  = (const float*)d_in[3];
    float* out = (float*)d_out;

    cudaFuncSetAttribute(k_knn, cudaFuncAttributeMaxDynamicSharedMemorySize,
                         SM_BYTES);

    k_sq      <<<dim3(NPTS / 256, BSZ), 256>>>(x);
    k_uv      <<<dim3(NPTS / 32,  BSZ), dim3(16, 16)>>>(x, W);
    k_knn     <<<dim3(NPTS / QT,  BSZ), 256, SM_BYTES>>>(x);
    k_gather  <<<dim3(NPTS / 64,  BSZ), dim3(64, 4)>>>();
    k_finalize<<<1, 64>>>(gamma, beta);
    k_out     <<<dim3(NPTS / 64,  BSZ), dim3(64, 4)>>>(out);
}

// round 9
// speedup vs baseline: 1.3517x; 1.3517x over previous
#include <cuda_runtime.h>
#include <cstdint>

#define BSZ  8
#define CDIM 64
#define NPTS 4096
#define KNN  20
#define OC   64
#define QT   128         // queries per block in k_knn

// ---------------- scratch (device globals; no allocation) ----------------
__device__ float g_sq [BSZ*NPTS];
__device__ float g_u  [BSZ*NPTS*OC];
__device__ float g_v  [BSZ*NPTS*OC];
__device__ int   g_idx[BSZ*NPTS*KNN];
__device__ float g_mxv[BSZ*NPTS*OC];
__device__ float g_mnv[BSZ*NPTS*OC];
__device__ float g_S1[OC];
__device__ float g_S2[OC];
__device__ float g_ga[OC];
__device__ float g_gb[OC];

// packed fp32x2 helpers (FFMA2 only reachable via PTX)
#define FMA2(acc, a, b) \
    asm("fma.rn.f32x2 %0, %1, %2, %0;" : "+l"(acc) : "l"(a), "l"(b))
#define DUP2(dst, f) \
    asm("mov.b64 %0, {%1, %1};" : "=l"(dst) : "f"(f))
#define UNPK2(lo, hi, src) \
    asm("mov.b64 {%0, %1}, %2;" : "=f"(lo), "=f"(hi) : "l"(src))

// ---------------- kernel 0: squared norms ----------------
__global__ __launch_bounds__(256) void k_sq(const float* __restrict__ x) {
    const int b = blockIdx.y;
    const int n = blockIdx.x * 256 + threadIdx.x;
    const float* xb = x + (size_t)b * CDIM * NPTS;
    float s = 0.f;
#pragma unroll 8
    for (int c = 0; c < CDIM; ++c) {
        float t = xb[c * NPTS + n];
        s += t * t;
    }
    g_sq[b * NPTS + n] = s;
}

// ---------------- kernel Z: zero stats (also pads launch order so that
// ncu's fixed capture slot (#4) lands on k_knn) ----------------
__global__ void k_zstat() {
    if (threadIdx.x < OC) {
        g_S1[threadIdx.x] = 0.f;
        g_S2[threadIdx.x] = 0.f;
    }
}

// ---------------- kernel A: u = W1*x, v = (W2-W1)*x, layout [b][n][o] ---
__global__ __launch_bounds__(256) void k_uv(const float* __restrict__ x,
                                            const float* __restrict__ W) {
    __shared__ float Wc[128 * 64];
    __shared__ float xt[64 * 32];
    const int b = blockIdx.y, n0 = blockIdx.x * 32;
    const int tx = threadIdx.x, ty = threadIdx.y, tid = ty * 16 + tx;

    for (int i = tid; i < 128 * 64; i += 256) {
        int r = i >> 6, c = i & 63;
        float wv;
        if (r < 64) wv = W[r * 128 + c];
        else        wv = W[(r - 64) * 128 + 64 + c] - W[(r - 64) * 128 + c];
        Wc[i] = wv;
    }
    const float* xb = x + (size_t)b * CDIM * NPTS;
    for (int i = tid; i < 64 * 32; i += 256) {
        int c = i >> 5, nn = i & 31;
        xt[i] = xb[c * NPTS + n0 + nn];
    }
    __syncthreads();

    float acc[8][2] = {};
#pragma unroll 8
    for (int c = 0; c < 64; ++c) {
        float2 bv = *(const float2*)&xt[c * 32 + tx * 2];
#pragma unroll
        for (int i = 0; i < 8; ++i) {
            float a = Wc[(ty * 8 + i) * 64 + c];
            acc[i][0] += a * bv.x;
            acc[i][1] += a * bv.y;
        }
    }
    __syncthreads();

    if (ty < 8) {
#pragma unroll
        for (int i = 0; i < 8; ++i) {
            Wc[(tx * 2 + 0) * 65 + ty * 8 + i] = acc[i][0];
            Wc[(tx * 2 + 1) * 65 + ty * 8 + i] = acc[i][1];
        }
    }
    __syncthreads();
    {
        float* dst = g_u + ((size_t)b * NPTS + n0) * OC;
        for (int i = tid; i < 32 * 64; i += 256) {
            int nn = i >> 6, oo = i & 63;
            dst[i] = Wc[nn * 65 + oo];
        }
    }
    __syncthreads();
    if (ty >= 8) {
#pragma unroll
        for (int i = 0; i < 8; ++i) {
            Wc[(tx * 2 + 0) * 65 + (ty - 8) * 8 + i] = acc[i][0];
            Wc[(tx * 2 + 1) * 65 + (ty - 8) * 8 + i] = acc[i][1];
        }
    }
    __syncthreads();
    {
        float* dst = g_v + ((size_t)b * NPTS + n0) * OC;
        for (int i = tid; i < 32 * 64; i += 256) {
            int nn = i >> 6, oo = i & 63;
            dst[i] = Wc[nn * 65 + oo];
        }
    }
}

// ---------------- kernel B: FFMA2 Gram + overlapped top-K ---------------
// smem (floats): qs[64*128] | Bs[64*64] | keys[128*66] | sqs[64]
#define KPAD  66
#define SM_QS   0
#define SM_BS   (64 * QT)
#define SM_KEYS (SM_BS + 64 * 64)
#define SM_SQS  (SM_KEYS + QT * KPAD)
#define SM_FLOATS (SM_SQS + 64)
#define SM_BYTES  (SM_FLOATS * 4)

__device__ __forceinline__ void insert_cand(float k, int m, float& tk, int& ti,
                                            float& thr, int& minl, int lane) {
    unsigned bal = __ballot_sync(0xffffffffu, k > thr);
    while (bal) {
        int src = __ffs(bal) - 1;
        bal &= bal - 1;
        float ck = __shfl_sync(0xffffffffu, k, src);
        int   cm = __shfl_sync(0xffffffffu, m, src);
        if (ck > thr) {                  // re-check: thr may have risen
            if (lane == minl) { tk = ck; ti = cm; }
            float mv = (lane < KNN) ? tk : 3.4e38f;
            int   ml = lane;
#pragma unroll
            for (int off = 16; off; off >>= 1) {
                float ov = __shfl_xor_sync(0xffffffffu, mv, off);
                int   ol = __shfl_xor_sync(0xffffffffu, ml, off);
                if (ov < mv || (ov == mv && ol < ml)) { mv = ov; ml = ol; }
            }
            thr = mv; minl = ml;         // uniform across warp
        }
    }
}

extern __shared__ float sm[];

__global__ __launch_bounds__(512, 2) void k_knn(const float* __restrict__ x) {
    float* qs   = sm + SM_QS;
    float* Bs   = sm + SM_BS;
    float* keys = sm + SM_KEYS;
    float* sqs  = sm + SM_SQS;

    const int b  = blockIdx.y;
    const int q0 = blockIdx.x * QT;
    const int tid  = threadIdx.x;
    const int tx   = tid & 15;          // colgroup: 4 candidate cols
    const int ty   = tid >> 4;          // rowgroup: 4 query rows (0..31)
    const int lane = tid & 31, warp = tid >> 5;   // 16 warps, 8 rows each
    const float* xb = x + (size_t)b * CDIM * NPTS;

    // load query tile [c][q]
    for (int i = tid; i < 64 * QT; i += 512) {
        int c = i >> 7, qq = i & 127;
        qs[i] = xb[c * NPTS + q0 + qq];
    }

    float tk[8], thr[8];
    int   ti[8], minl[8];
#pragma unroll
    for (int r = 0; r < 8; ++r) {
        tk[r] = -3.4e38f; ti[r] = 0; thr[r] = -3.4e38f; minl[r] = 0;
    }

    for (int t = 0; t < NPTS / 64; ++t) {
        const int m0 = t * 64;
        __syncthreads();   // [1] qs/keys(t-1) written by all; Bs(t-1) fully read

        // load this tile's B + sq (LDG latency overlaps selection below)
        for (int i = tid; i < 64 * 64; i += 512) {
            int c = i >> 6, mm = i & 63;
            Bs[i] = xb[c * NPTS + m0 + mm];
        }
        if (tid < 64) sqs[tid] = g_sq[b * NPTS + m0 + tid];

        // selection for PREVIOUS tile's keys (pure LDS + ballot)
        if (t > 0) {
            const int mp = m0 - 64;
#pragma unroll
            for (int r = 0; r < 8; ++r) {
                const float* krow = &keys[(warp * 8 + r) * KPAD];
                float k0 = krow[lane];
                float k1 = krow[32 + lane];
                insert_cand(k0, mp + lane,      tk[r], ti[r], thr[r], minl[r], lane);
                insert_cand(k1, mp + 32 + lane, tk[r], ti[r], thr[r], minl[r], lane);
            }
        }
        __syncthreads();   // [2] Bs/sqs visible; keys(t-1) consumed

        // --- 4x4 microtile: 2 row-pairs x 4 cols of f32x2 FFMA2 ---
        unsigned long long acc[2][4];
#pragma unroll
        for (int i = 0; i < 2; ++i)
#pragma unroll
            for (int j = 0; j < 4; ++j) acc[i][j] = 0ull;

#pragma unroll 8
        for (int c = 0; c < 64; ++c) {
            ulonglong2 A = *(const ulonglong2*)&qs[c * QT + ty * 4];
            float4 bq = *(const float4*)&Bs[c * 64 + tx * 4];
            unsigned long long d0, d1, d2, d3;
            DUP2(d0, bq.x); DUP2(d1, bq.y); DUP2(d2, bq.z); DUP2(d3, bq.w);
            FMA2(acc[0][0], A.x, d0); FMA2(acc[0][1], A.x, d1);
            FMA2(acc[0][2], A.x, d2); FMA2(acc[0][3], A.x, d3);
            FMA2(acc[1][0], A.y, d0); FMA2(acc[1][1], A.y, d1);
            FMA2(acc[1][2], A.y, d2); FMA2(acc[1][3], A.y, d3);
        }

        // keys = 2*dot - |m|^2  (final values; selection needs no math)
        float4 sv = *(const float4*)&sqs[tx * 4];
#pragma unroll
        for (int i = 0; i < 2; ++i) {
            float lo, hi;
            float* krow0 = &keys[(ty * 4 + 2 * i) * KPAD + tx * 4];
            float* krow1 = krow0 + KPAD;
            UNPK2(lo, hi, acc[i][0]);
            krow0[0] = fmaf(2.f, lo, -sv.x); krow1[0] = fmaf(2.f, hi, -sv.x);
            UNPK2(lo, hi, acc[i][1]);
            krow0[1] = fmaf(2.f, lo, -sv.y); krow1[1] = fmaf(2.f, hi, -sv.y);
            UNPK2(lo, hi, acc[i][2]);
            krow0[2] = fmaf(2.f, lo, -sv.z); krow1[2] = fmaf(2.f, hi, -sv.z);
            UNPK2(lo, hi, acc[i][3]);
            krow0[3] = fmaf(2.f, lo, -sv.w); krow1[3] = fmaf(2.f, hi, -sv.w);
        }
    }

    // final tile's selection
    __syncthreads();
    {
        const int mp = NPTS - 64;
#pragma unroll
        for (int r = 0; r < 8; ++r) {
            const float* krow = &keys[(warp * 8 + r) * KPAD];
            float k0 = krow[lane];
            float k1 = krow[32 + lane];
            insert_cand(k0, mp + lane,      tk[r], ti[r], thr[r], minl[r], lane);
            insert_cand(k1, mp + 32 + lane, tk[r], ti[r], thr[r], minl[r], lane);
        }
    }

    if (lane < KNN) {
#pragma unroll
        for (int r = 0; r < 8; ++r)
            g_idx[((size_t)b * NPTS + q0 + warp * 8 + r) * KNN + lane] = ti[r];
    }
}

// ---------------- kernel C: one gather pass: max/min + BN stats ----------
__global__ __launch_bounds__(256) void k_gather() {
    __shared__ int   sidx[4][KNN];
    __shared__ float red[2][4][64];
    const int o = threadIdx.x;
    const int py = threadIdx.y;
    const int tid = py * 64 + o;
    const int b = blockIdx.y;
    const int n0 = blockIdx.x * 64;
    const float* ub = g_u + (size_t)b * NPTS * OC;
    float s1 = 0.f, s2 = 0.f;

    for (int it = 0; it < 16; ++it) {
        __syncthreads();
        if (tid < 4 * KNN) {
            int g = tid / KNN, j = tid % KNN;
            sidx[g][j] = g_idx[((size_t)b * NPTS + n0 + it * 4 + g) * KNN + j];
        }
        __syncthreads();
        const int n = n0 + it * 4 + py;
        float s = 0.f, q = 0.f, mx = -3.4e38f, mn = 3.4e38f;
#pragma unroll
        for (int j = 0; j < KNN; ++j) {
            float val = ub[(size_t)sidx[py][j] * OC + o];
            s += val; q += val * val;
            mx = fmaxf(mx, val); mn = fminf(mn, val);
        }
        const size_t off = ((size_t)b * NPTS + n) * OC + o;
        float vv = g_v[off];
        g_mxv[off] = mx + vv;
        g_mnv[off] = mn + vv;
        s1 += (float)KNN * vv + s;
        s2 += (float)KNN * vv * vv + 2.f * vv * s + q;
    }
    red[0][py][o] = s1;
    red[1][py][o] = s2;
    __syncthreads();
    if (py == 0) {
        float a = red[0][0][o] + red[0][1][o] + red[0][2][o] + red[0][3][o];
        float c = red[1][0][o] + red[1][1][o] + red[1][2][o] + red[1][3][o];
        atomicAdd(&g_S1[o], a);
        atomicAdd(&g_S2[o], c);
    }
}

// ---------------- kernel D: finalize BN affine coefficients --------------
__global__ void k_finalize(const float* __restrict__ gamma,
                           const float* __restrict__ beta) {
    int o = threadIdx.x;
    const float M = (float)BSZ * (float)NPTS * (float)KNN;
    float mean = g_S1[o] / M;
    float var  = g_S2[o] / M - mean * mean;
    float a = gamma[o] * rsqrtf(var + 1e-5f);
    g_ga[o] = a;
    g_gb[o] = beta[o] - mean * a;
}

// ---------------- kernel E: affine + LeakyReLU + transpose to [b][o][n] --
__global__ __launch_bounds__(256) void k_out(float* __restrict__ out) {
    __shared__ float tile[64][65];
    const int o = threadIdx.x, ty = threadIdx.y;
    const int b = blockIdx.y, n0 = blockIdx.x * 64;
    const float a = g_ga[o], bc = g_gb[o];
#pragma unroll
    for (int it = 0; it < 16; ++it) {
        int nl = it * 4 + ty;
        size_t off = ((size_t)b * NPTS + n0 + nl) * OC + o;
        float raw = (a >= 0.f) ? g_mxv[off] : g_mnv[off];
        float val = fmaf(a, raw, bc);
        tile[nl][o] = (val >= 0.f) ? val : 0.2f * val;
    }
    __syncthreads();
#pragma unroll
    for (int it = 0; it < 16; ++it) {
        int oo = it * 4 + ty;
        out[((size_t)b * OC + oo) * NPTS + n0 + o] = tile[o][oo];
    }
}

// ---------------- launch ----------------
extern "C" void kernel_launch(void* const* d_in, const int* in_sizes, int n_in,
                              void* d_out, int out_size) {
    const float* x     = (const float*)d_in[0];
    const float* W     = (const float*)d_in[1];
    const float* gamma = (const float*)d_in[2];
    const float* beta  = (const float*)d_in[3];
    float* out = (float*)d_out;

    cudaFuncSetAttribute(k_knn, cudaFuncAttributeMaxDynamicSharedMemorySize,
                         SM_BYTES);

    k_sq      <<<dim3(NPTS / 256, BSZ), 256>>>(x);
    k_uv      <<<dim3(NPTS / 32,  BSZ), dim3(16, 16)>>>(x, W);
    k_zstat   <<<1, 64>>>();                        // pads slot 3 -> k_knn profiled
    k_knn     <<<dim3(NPTS / QT,  BSZ), 512, SM_BYTES>>>(x);
    k_gather  <<<dim3(NPTS / 64,  BSZ), dim3(64, 4)>>>();
    k_finalize<<<1, 64>>>(gamma, beta);
    k_out     <<<dim3(NPTS / 64,  BSZ), dim3(64, 4)>>>(out);
}

// round 10
// speedup vs baseline: 1.3546x; 1.0021x over previous
#include <cuda_runtime.h>
#include <cstdint>

#define BSZ  8
#define CDIM 64
#define NPTS 4096
#define KNN  20
#define OC   64
#define QT   128         // queries per block in k_knn

// ---------------- scratch (device globals; no allocation) ----------------
__device__ float g_sq [BSZ*NPTS];
__device__ float g_u  [BSZ*NPTS*OC];
__device__ float g_v  [BSZ*NPTS*OC];
__device__ int   g_idx[BSZ*NPTS*KNN];
__device__ float g_mxv[BSZ*NPTS*OC];
__device__ float g_mnv[BSZ*NPTS*OC];
__device__ float g_S1[OC];
__device__ float g_S2[OC];
__device__ float g_ga[OC];
__device__ float g_gb[OC];

// packed fp32x2 helpers (FFMA2 only reachable via PTX)
#define FMA2(acc, a, b) \
    asm("fma.rn.f32x2 %0, %1, %2, %0;" : "+l"(acc) : "l"(a), "l"(b))
#define DUP2(dst, f) \
    asm("mov.b64 %0, {%1, %1};" : "=l"(dst) : "f"(f))
#define UNPK2(lo, hi, src) \
    asm("mov.b64 {%0, %1}, %2;" : "=f"(lo), "=f"(hi) : "l"(src))

// ---------------- kernel 0: squared norms ----------------
__global__ __launch_bounds__(256) void k_sq(const float* __restrict__ x) {
    const int b = blockIdx.y;
    const int n = blockIdx.x * 256 + threadIdx.x;
    const float* xb = x + (size_t)b * CDIM * NPTS;
    float s = 0.f;
#pragma unroll 8
    for (int c = 0; c < CDIM; ++c) {
        float t = xb[c * NPTS + n];
        s += t * t;
    }
    g_sq[b * NPTS + n] = s;
}

// ---------------- kernel Z: zero stats (pads launch order so ncu's
// fixed capture slot lands on k_knn) ----------------
__global__ void k_zstat() {
    if (threadIdx.x < OC) {
        g_S1[threadIdx.x] = 0.f;
        g_S2[threadIdx.x] = 0.f;
    }
}

// ---------------- kernel A: u = W1*x, v = (W2-W1)*x, layout [b][n][o] ---
__global__ __launch_bounds__(256) void k_uv(const float* __restrict__ x,
                                            const float* __restrict__ W) {
    __shared__ float Wc[128 * 64];
    __shared__ float xt[64 * 32];
    const int b = blockIdx.y, n0 = blockIdx.x * 32;
    const int tx = threadIdx.x, ty = threadIdx.y, tid = ty * 16 + tx;

    for (int i = tid; i < 128 * 64; i += 256) {
        int r = i >> 6, c = i & 63;
        float wv;
        if (r < 64) wv = W[r * 128 + c];
        else        wv = W[(r - 64) * 128 + 64 + c] - W[(r - 64) * 128 + c];
        Wc[i] = wv;
    }
    const float* xb = x + (size_t)b * CDIM * NPTS;
    for (int i = tid; i < 64 * 32; i += 256) {
        int c = i >> 5, nn = i & 31;
        xt[i] = xb[c * NPTS + n0 + nn];
    }
    __syncthreads();

    float acc[8][2] = {};
#pragma unroll 8
    for (int c = 0; c < 64; ++c) {
        float2 bv = *(const float2*)&xt[c * 32 + tx * 2];
#pragma unroll
        for (int i = 0; i < 8; ++i) {
            float a = Wc[(ty * 8 + i) * 64 + c];
            acc[i][0] += a * bv.x;
            acc[i][1] += a * bv.y;
        }
    }
    __syncthreads();

    if (ty < 8) {
#pragma unroll
        for (int i = 0; i < 8; ++i) {
            Wc[(tx * 2 + 0) * 65 + ty * 8 + i] = acc[i][0];
            Wc[(tx * 2 + 1) * 65 + ty * 8 + i] = acc[i][1];
        }
    }
    __syncthreads();
    {
        float* dst = g_u + ((size_t)b * NPTS + n0) * OC;
        for (int i = tid; i < 32 * 64; i += 256) {
            int nn = i >> 6, oo = i & 63;
            dst[i] = Wc[nn * 65 + oo];
        }
    }
    __syncthreads();
    if (ty >= 8) {
#pragma unroll
        for (int i = 0; i < 8; ++i) {
            Wc[(tx * 2 + 0) * 65 + (ty - 8) * 8 + i] = acc[i][0];
            Wc[(tx * 2 + 1) * 65 + (ty - 8) * 8 + i] = acc[i][1];
        }
    }
    __syncthreads();
    {
        float* dst = g_v + ((size_t)b * NPTS + n0) * OC;
        for (int i = tid; i < 32 * 64; i += 256) {
            int nn = i >> 6, oo = i & 63;
            dst[i] = Wc[nn * 65 + oo];
        }
    }
}

// ---------------- kernel B: FFMA2 Gram, 1 barrier/tile, staged loads ----
// smem (floats): qs[64*128] | Bs[2][64*64] | keys[128*66] | sqs[2][64]
#define KPAD  66
#define SM_QS   0
#define SM_BS   (64 * QT)
#define SM_KEYS (SM_BS + 2 * 64 * 64)
#define SM_SQS  (SM_KEYS + QT * KPAD)
#define SM_FLOATS (SM_SQS + 2 * 64)
#define SM_BYTES  (SM_FLOATS * 4)

__device__ __forceinline__ void insert_cand(float k, int m, float& tk, int& ti,
                                            float& thr, int& minl, int lane) {
    unsigned bal = __ballot_sync(0xffffffffu, k > thr);
    while (bal) {
        int src = __ffs(bal) - 1;
        bal &= bal - 1;
        float ck = __shfl_sync(0xffffffffu, k, src);
        int   cm = __shfl_sync(0xffffffffu, m, src);
        if (ck > thr) {                  // re-check: thr may have risen
            if (lane == minl) { tk = ck; ti = cm; }
            float mv = (lane < KNN) ? tk : 3.4e38f;
            int   ml = lane;
#pragma unroll
            for (int off = 16; off; off >>= 1) {
                float ov = __shfl_xor_sync(0xffffffffu, mv, off);
                int   ol = __shfl_xor_sync(0xffffffffu, ml, off);
                if (ov < mv || (ov == mv && ol < ml)) { mv = ov; ml = ol; }
            }
            thr = mv; minl = ml;         // uniform across warp
        }
    }
}

extern __shared__ float sm[];

__global__ __launch_bounds__(512, 2) void k_knn(const float* __restrict__ x) {
    float* qs   = sm + SM_QS;
    float* BsA  = sm + SM_BS;            // Bs[2][4096]
    float* keys = sm + SM_KEYS;
    float* sqsA = sm + SM_SQS;           // sqs[2][64]

    const int b  = blockIdx.y;
    const int q0 = blockIdx.x * QT;
    const int tid  = threadIdx.x;
    const int tx   = tid & 15;          // colgroup: 4 candidate cols
    const int ty   = tid >> 4;          // rowgroup: 4 query rows (0..31)
    const int lane = tid & 31, warp = tid >> 5;   // 16 warps, 8 rows each
    const float* xb = x + (size_t)b * CDIM * NPTS;

    // load query tile [c][q]
    for (int i = tid; i < 64 * QT; i += 512) {
        int c = i >> 7, qq = i & 127;
        qs[i] = xb[c * NPTS + q0 + qq];
    }
    // tile 0 of B + sq (direct; one-time exposure)
    for (int i = tid; i < 64 * 64; i += 512) {
        int c = i >> 6, mm = i & 63;
        BsA[i] = xb[c * NPTS + mm];
    }
    if (tid < 64) sqsA[tid] = g_sq[b * NPTS + tid];

    float tk[8], thr[8];
    int   ti[8], minl[8];
#pragma unroll
    for (int r = 0; r < 8; ++r) {
        tk[r] = -3.4e38f; ti[r] = 0; thr[r] = -3.4e38f; minl[r] = 0;
    }
    __syncthreads();

    // float4-index mapping for staged B loads: i4 in [0,1024), thread does 2
    const int i40 = tid, i41 = tid + 512;

    for (int t = 0; t < NPTS / 64; ++t) {
        const int cur = t & 1;
        const int m0 = t * 64;
        float* Bs  = BsA + cur * 4096;
        float* sqs = sqsA + cur * 64;

        // ---- stage next B tile into registers (latency hidden by compute)
        float4 stg0, stg1;
        float sqstg = 0.f;
        if (t + 1 < NPTS / 64) {
            const int m0n = m0 + 64;
            stg0 = *(const float4*)&xb[(i40 >> 4) * NPTS + m0n + (i40 & 15) * 4];
            stg1 = *(const float4*)&xb[(i41 >> 4) * NPTS + m0n + (i41 & 15) * 4];
            if (tid < 64) sqstg = g_sq[b * NPTS + m0n + tid];
        }

        // --- 4x4 microtile: 2 row-pairs x 4 cols of f32x2 FFMA2 ---
        unsigned long long acc[2][4];
#pragma unroll
        for (int i = 0; i < 2; ++i)
#pragma unroll
            for (int j = 0; j < 4; ++j) acc[i][j] = 0ull;

#pragma unroll 8
        for (int c = 0; c < 64; ++c) {
            ulonglong2 A = *(const ulonglong2*)&qs[c * QT + ty * 4];
            float4 bq = *(const float4*)&Bs[c * 64 + tx * 4];
            unsigned long long d0, d1, d2, d3;
            DUP2(d0, bq.x); DUP2(d1, bq.y); DUP2(d2, bq.z); DUP2(d3, bq.w);
            FMA2(acc[0][0], A.x, d0); FMA2(acc[0][1], A.x, d1);
            FMA2(acc[0][2], A.x, d2); FMA2(acc[0][3], A.x, d3);
            FMA2(acc[1][0], A.y, d0); FMA2(acc[1][1], A.y, d1);
            FMA2(acc[1][2], A.y, d2); FMA2(acc[1][3], A.y, d3);
        }

        // keys = 2*dot - |m|^2  (warp-private rows: warp w wrote rows 8w..8w+7)
        float4 sv = *(const float4*)&sqs[tx * 4];
#pragma unroll
        for (int i = 0; i < 2; ++i) {
            float lo, hi;
            float* krow0 = &keys[(ty * 4 + 2 * i) * KPAD + tx * 4];
            float* krow1 = krow0 + KPAD;
            UNPK2(lo, hi, acc[i][0]);
            krow0[0] = fmaf(2.f, lo, -sv.x); krow1[0] = fmaf(2.f, hi, -sv.x);
            UNPK2(lo, hi, acc[i][1]);
            krow0[1] = fmaf(2.f, lo, -sv.y); krow1[1] = fmaf(2.f, hi, -sv.y);
            UNPK2(lo, hi, acc[i][2]);
            krow0[2] = fmaf(2.f, lo, -sv.z); krow1[2] = fmaf(2.f, hi, -sv.z);
            UNPK2(lo, hi, acc[i][3]);
            krow0[3] = fmaf(2.f, lo, -sv.w); krow1[3] = fmaf(2.f, hi, -sv.w);
        }
        __syncwarp();     // intra-warp: keys visible to sibling lanes

        // ---- selection (no block barrier needed: keys are warp-private)
#pragma unroll
        for (int r = 0; r < 8; ++r) {
            const float* krow = &keys[(warp * 8 + r) * KPAD];
            float k0 = krow[lane];
            float k1 = krow[32 + lane];
            insert_cand(k0, m0 + lane,      tk[r], ti[r], thr[r], minl[r], lane);
            insert_cand(k1, m0 + 32 + lane, tk[r], ti[r], thr[r], minl[r], lane);
        }
        __syncwarp();     // selection reads done before next epilogue overwrite

        // ---- commit staged tile to the other buffer
        if (t + 1 < NPTS / 64) {
            float* Bn = BsA + (cur ^ 1) * 4096;
            *(float4*)&Bn[i40 * 4] = stg0;
            *(float4*)&Bn[i41 * 4] = stg1;
            if (tid < 64) sqsA[(cur ^ 1) * 64 + tid] = sqstg;
        }
        __syncthreads();  // [single barrier] next Bs ready; cur fully consumed
    }

    if (lane < KNN) {
#pragma unroll
        for (int r = 0; r < 8; ++r)
            g_idx[((size_t)b * NPTS + q0 + warp * 8 + r) * KNN + lane] = ti[r];
    }
}

// ---------------- kernel C: one gather pass: max/min + BN stats ----------
__global__ __launch_bounds__(256) void k_gather() {
    __shared__ int   sidx[4][KNN];
    __shared__ float red[2][4][64];
    const int o = threadIdx.x;
    const int py = threadIdx.y;
    const int tid = py * 64 + o;
    const int b = blockIdx.y;
    const int n0 = blockIdx.x * 64;
    const float* ub = g_u + (size_t)b * NPTS * OC;
    float s1 = 0.f, s2 = 0.f;

    for (int it = 0; it < 16; ++it) {
        __syncthreads();
        if (tid < 4 * KNN) {
            int g = tid / KNN, j = tid % KNN;
            sidx[g][j] = g_idx[((size_t)b * NPTS + n0 + it * 4 + g) * KNN + j];
        }
        __syncthreads();
        const int n = n0 + it * 4 + py;
        float s = 0.f, q = 0.f, mx = -3.4e38f, mn = 3.4e38f;
#pragma unroll
        for (int j = 0; j < KNN; ++j) {
            float val = ub[(size_t)sidx[py][j] * OC + o];
            s += val; q += val * val;
            mx = fmaxf(mx, val); mn = fminf(mn, val);
        }
        const size_t off = ((size_t)b * NPTS + n) * OC + o;
        float vv = g_v[off];
        g_mxv[off] = mx + vv;
        g_mnv[off] = mn + vv;
        s1 += (float)KNN * vv + s;
        s2 += (float)KNN * vv * vv + 2.f * vv * s + q;
    }
    red[0][py][o] = s1;
    red[1][py][o] = s2;
    __syncthreads();
    if (py == 0) {
        float a = red[0][0][o] + red[0][1][o] + red[0][2][o] + red[0][3][o];
        float c = red[1][0][o] + red[1][1][o] + red[1][2][o] + red[1][3][o];
        atomicAdd(&g_S1[o], a);
        atomicAdd(&g_S2[o], c);
    }
}

// ---------------- kernel D: finalize BN affine coefficients --------------
__global__ void k_finalize(const float* __restrict__ gamma,
                           const float* __restrict__ beta) {
    int o = threadIdx.x;
    const float M = (float)BSZ * (float)NPTS * (float)KNN;
    float mean = g_S1[o] / M;
    float var  = g_S2[o] / M - mean * mean;
    float a = gamma[o] * rsqrtf(var + 1e-5f);
    g_ga[o] = a;
    g_gb[o] = beta[o] - mean * a;
}

// ---------------- kernel E: affine + LeakyReLU + transpose to [b][o][n] --
__global__ __launch_bounds__(256) void k_out(float* __restrict__ out) {
    __shared__ float tile[64][65];
    const int o = threadIdx.x, ty = threadIdx.y;
    const int b = blockIdx.y, n0 = blockIdx.x * 64;
    const float a = g_ga[o], bc = g_gb[o];
#pragma unroll
    for (int it = 0; it < 16; ++it) {
        int nl = it * 4 + ty;
        size_t off = ((size_t)b * NPTS + n0 + nl) * OC + o;
        float raw = (a >= 0.f) ? g_mxv[off] : g_mnv[off];
        float val = fmaf(a, raw, bc);
        tile[nl][o] = (val >= 0.f) ? val : 0.2f * val;
    }
    __syncthreads();
#pragma unroll
    for (int it = 0; it < 16; ++it) {
        int oo = it * 4 + ty;
        out[((size_t)b * OC + oo) * NPTS + n0 + o] = tile[o][oo];
    }
}

// ---------------- launch ----------------
extern "C" void kernel_launch(void* const* d_in, const int* in_sizes, int n_in,
                              void* d_out, int out_size) {
    const float* x     = (const float*)d_in[0];
    const float* W     = (const float*)d_in[1];
    const float* gamma = (const float*)d_in[2];
    const float* beta  = (const float*)d_in[3];
    float* out = (float*)d_out;

    cudaFuncSetAttribute(k_knn, cudaFuncAttributeMaxDynamicSharedMemorySize,
                         SM_BYTES);

    k_sq      <<<dim3(NPTS / 256, BSZ), 256>>>(x);
    k_uv      <<<dim3(NPTS / 32,  BSZ), dim3(16, 16)>>>(x, W);
    k_zstat   <<<1, 64>>>();                        // pads slot 3 -> k_knn profiled
    k_knn     <<<dim3(NPTS / QT,  BSZ), 512, SM_BYTES>>>(x);
    k_gather  <<<dim3(NPTS / 64,  BSZ), dim3(64, 4)>>>();
    k_finalize<<<1, 64>>>(gamma, beta);
    k_out     <<<dim3(NPTS / 64,  BSZ), dim3(64, 4)>>>(out);
}